// round 15
// baseline (speedup 1.0000x reference)
#include <cuda_runtime.h>
#include <cuda_fp16.h>
#include <math.h>
#include <stdint.h>

#define TSEQ 4096
#define NH   16
#define NKV  4
#define HDIM 64
#define DIM  1024
#define QKVD 1536
#define KVOFF 1024
#define VOFF  1280

// ---------------- scratch (device globals; no cudaMalloc allowed) ----------
// float-declared, but several are used as __half (half capacity needed).
__device__ float g_qkv[TSEQ * QKVD];       // f32 (gemm1 output, prep input)
__device__ float g_q[NH * TSEQ * HDIM];    // half, d-axis word-perm8, pre-scaled by gain*cs
__device__ float g_k[NKV * TSEQ * HDIM];   // half, d-axis word-perm8
__device__ float g_v[NKV * TSEQ * HDIM];   // half, TRANSPOSED [kv][d][t], t word-perm8
__device__ float g_y[TSEQ * DIM];          // half, DIM-axis word-perm8
__device__ float g_xr[TSEQ * DIM];         // half, K-axis word-perm8
__device__ float g_wq[QKVD * DIM];         // half, K-axis word-perm8
__device__ float g_wp[DIM * DIM];          // half, K-axis word-perm8
__device__ float g_invf[32];

// ---------------- helpers ---------------------------------------------------
__device__ __forceinline__ uint32_t f2h2(float lo, float hi) {
    __half2 h = __floats2half2_rn(lo, hi);   // .x = lo half
    return *(uint32_t*)&h;
}
__device__ __forceinline__ uint32_t h2ex2(uint32_t x) {
    uint32_t r;
    asm("ex2.approx.f16x2 %0, %1;" : "=r"(r) : "r"(x));
    return r;
}
__device__ __forceinline__ void mma_f16(float c[4], const uint32_t a[4],
                                        const uint32_t b[2]) {
    asm volatile(
        "mma.sync.aligned.m16n8k16.row.col.f32.f16.f16.f32 "
        "{%0,%1,%2,%3}, {%4,%5,%6,%7}, {%8,%9}, {%0,%1,%2,%3};"
        : "+f"(c[0]), "+f"(c[1]), "+f"(c[2]), "+f"(c[3])
        : "r"(a[0]), "r"(a[1]), "r"(a[2]), "r"(a[3]), "r"(b[0]), "r"(b[1]));
}
__device__ __forceinline__ void cp16(void* smem_dst, const void* gsrc) {
    uint32_t s = (uint32_t)__cvta_generic_to_shared(smem_dst);
    asm volatile("cp.async.ca.shared.global [%0], [%1], 16;" :: "r"(s), "l"(gsrc));
}
// word-perm within each 8-word (16-half) block: word w -> 2*(w%4) + (w/4)%2
__device__ __forceinline__ int wp8(int w) {
    return (w & ~7) | ((w & 3) << 1) | ((w >> 2) & 1);
}

// ---------------- one-shot inv_freq ----------------------------------------
__global__ void freq_kernel() {
    int l = threadIdx.x;
    g_invf[l] = (float)(1.0 / pow(10000.0, (double)l * (1.0 / 32.0)));
}

// ---------------- pre-round: f32 -> f16, K-axis word-perm8 -----------------
__global__ __launch_bounds__(256) void round3h_kernel(
    const float* __restrict__ a, __half* __restrict__ da, int n1,
    const float* __restrict__ b, __half* __restrict__ db, int n2,
    const float* __restrict__ c, __half* __restrict__ dc, int n3) {
    int i = blockIdx.x * blockDim.x + threadIdx.x;
    int total = n1 + n2 + n3;
    for (; i < total; i += gridDim.x * blockDim.x) {
        const float* s;
        __half* d;
        int j = i;
        if (j < n1) { s = a; d = da; }
        else if (j < n1 + n2) { j -= n1; s = b; d = db; }
        else { j -= n1 + n2; s = c; d = dc; }
        float4 v = ((const float4*)s)[j];
        uint32_t* du = (uint32_t*)d;
        int w0 = j << 1;
        du[wp8(w0)]     = f2h2(v.x, v.y);
        du[wp8(w0 + 1)] = f2h2(v.z, v.w);
    }
}

// ---------------- fp16 GEMM: C[M,N] = A[M,K] * B[N,K]^T --------------------
// A,B half, K-axis word-perm8. 128x128 tile, 8 warps (2m x 4n), k-step 32,
// 3-stage cp.async. smem row stride 24 words (16 data + 8 pad), conflict-free.
#define GRS 24                       // words per row in smem
#define GSTG (128 * GRS)             // per-tensor per-stage words
#define GEMM_SMEM_BYTES (3 * 2 * GSTG * 4)

__global__ __launch_bounds__(256, 2) void gemm_h(const __half* __restrict__ A,
                                                 const __half* __restrict__ B,
                                                 float* __restrict__ C,
                                                 int M, int N, int K) {
    extern __shared__ __align__(16) uint32_t gsm[];
    const int tid = threadIdx.x;
    const int m0 = blockIdx.y * 128;
    const int n0 = blockIdx.x * 128;
    const int warp = tid >> 5;
    const int lane = tid & 31;
    const int gid = lane >> 2;
    const int tig = lane & 3;
    const int wm = (warp & 1) * 64;
    const int wn = (warp >> 1) * 32;

    auto issue = [&](int it) {
        int k0 = it * 32;                       // halves
        uint32_t* As = gsm + (it % 3) * 2 * GSTG;
        uint32_t* Bs = As + GSTG;
#pragma unroll
        for (int i = 0; i < 4; i++) {
            int id = tid + 256 * i;             // 0..1023
            int rid = id & 511;
            int row = rid >> 2, ch = (rid & 3) * 8;   // 8-half chunks
            const __half* src = ((id < 512)
                ? A + (size_t)(m0 + row) * K
                : B + (size_t)(n0 + row) * K) + k0 + ch;
            uint32_t* dst = ((id < 512) ? As : Bs) + row * GRS + (ch >> 1);
            cp16(dst, src);
        }
        asm volatile("cp.async.commit_group;");
    };

    float acc[4][4][4];
#pragma unroll
    for (int mi = 0; mi < 4; mi++)
#pragma unroll
        for (int ni = 0; ni < 4; ni++)
#pragma unroll
            for (int f = 0; f < 4; f++) acc[mi][ni][f] = 0.f;

    const int nIter = K / 32;
    issue(0); issue(1);

    for (int it = 0; it < nIter; it++) {
        asm volatile("cp.async.wait_group 1;");
        __syncthreads();
        if (it + 2 < nIter) issue(it + 2);
        else asm volatile("cp.async.commit_group;");

        const uint32_t* As = gsm + (it % 3) * 2 * GSTG;
        const uint32_t* Bs = As + GSTG;
#pragma unroll
        for (int s = 0; s < 2; s++) {
            uint32_t af[4][4], bf[4][2];
#pragma unroll
            for (int mi = 0; mi < 4; mi++) {
                int r = (wm + 16 * mi + gid) * GRS + 8 * s + 2 * tig;
                uint2 lo = *(const uint2*)&As[r];
                uint2 hi = *(const uint2*)&As[r + 8 * GRS];
                af[mi][0] = lo.x; af[mi][1] = hi.x;
                af[mi][2] = lo.y; af[mi][3] = hi.y;
            }
#pragma unroll
            for (int ni = 0; ni < 4; ni++) {
                uint2 b2 = *(const uint2*)&Bs[(wn + 8 * ni + gid) * GRS + 8 * s + 2 * tig];
                bf[ni][0] = b2.x; bf[ni][1] = b2.y;
            }
#pragma unroll
            for (int mi = 0; mi < 4; mi++)
#pragma unroll
                for (int ni = 0; ni < 4; ni++) mma_f16(acc[mi][ni], af[mi], bf[ni]);
        }
    }

#pragma unroll
    for (int mi = 0; mi < 4; mi++) {
        int r0 = m0 + wm + 16 * mi + gid;
#pragma unroll
        for (int ni = 0; ni < 4; ni++) {
            int c = n0 + wn + 8 * ni + 2 * tig;
            *(float2*)(C + (size_t)r0 * N + c) = make_float2(acc[mi][ni][0], acc[mi][ni][1]);
            *(float2*)(C + (size_t)(r0 + 8) * N + c) = make_float2(acc[mi][ni][2], acc[mi][ni][3]);
        }
    }
}

// ---------------- prep: RMSNorm + RoPE + gain -> half, d word-perm8 --------
// Q is additionally pre-scaled by cs = (1/8)*log2(e), so the attention S-mma
// directly produces log2-domain scores.
__global__ __launch_bounds__(256) void prep_kernel(const float* __restrict__ qkv,
                                                   const float* __restrict__ gain) {
    const int warp = blockIdx.x * 8 + (threadIdx.x >> 5);
    const int lane = threadIdx.x & 31;
    const int NQ = TSEQ * NH;
    const int NK = TSEQ * NKV;
    if (warp >= NQ + NK) return;

    const float cs = 0.18033688011112042f;
    int t, off;
    float g;
    __half* dst;
    if (warp < NQ) {
        t = warp / NH;
        int h = warp % NH;
        off = h * HDIM;
        g = gain[h] * cs;
        dst = (__half*)g_q + ((size_t)h * TSEQ + t) * HDIM;
    } else {
        int w = warp - NQ;
        t = w / NKV;
        int kv = w % NKV;
        off = KVOFF + kv * HDIM;
        g = 1.0f;
        dst = (__half*)g_k + ((size_t)kv * TSEQ + t) * HDIM;
    }
    const float* src = qkv + (size_t)t * QKVD + off;
    float x1 = src[lane], x2 = src[lane + 32];
    float ss = x1 * x1 + x2 * x2;
    ss += __shfl_xor_sync(0xffffffffu, ss, 16);
    ss += __shfl_xor_sync(0xffffffffu, ss, 8);
    ss += __shfl_xor_sync(0xffffffffu, ss, 4);
    ss += __shfl_xor_sync(0xffffffffu, ss, 2);
    ss += __shfl_xor_sync(0xffffffffu, ss, 1);
    float r = rsqrtf(ss * (1.0f / 64.0f) + 1.1920929e-07f);
    x1 *= r; x2 *= r;
    float fr = (float)t * g_invf[lane];
    float s, c;
    sincosf(fr, &s, &c);
    int e1 = lane, e2 = lane + 32;
    dst[2 * wp8(e1 >> 1) + (e1 & 1)] = __float2half_rn((x1 * c + x2 * s) * g);
    dst[2 * wp8(e2 >> 1) + (e2 & 1)] = __float2half_rn((x2 * c - x1 * s) * g);
}

// ---------------- V transpose: qkv v-slice -> half [kv][d][t], t perm8 -----
__global__ __launch_bounds__(256) void vtrans_kernel(const float* __restrict__ qkv) {
    __shared__ float ts[32][33];
    const int tx = threadIdx.x & 31;
    const int ty = threadIdx.x >> 5;
    const int t0 = blockIdx.x * 32;
    const int kv = blockIdx.y >> 1;
    const int d0 = (blockIdx.y & 1) * 32;
#pragma unroll
    for (int i = 0; i < 4; i++) {
        int row = ty + 8 * i;
        ts[row][tx] = qkv[(size_t)(t0 + row) * QKVD + VOFF + kv * HDIM + d0 + tx];
    }
    __syncthreads();
    __half* vb = (__half*)g_v + ((size_t)kv * HDIM) * TSEQ;
    int t = t0 + tx;
    int tpos = 2 * wp8(t >> 1) + (t & 1);
#pragma unroll
    for (int i = 0; i < 4; i++) {
        int d = d0 + ty + 8 * i;
        vb[(size_t)d * TSEQ + tpos] = __float2half_rn(ts[tx][ty + 8 * i]);
    }
}

// ---------------- flash attention: fp16 mma, 128-row Q tile, 8 warps -------
// Q pre-scaled by cs -> S is directly log2-domain. No bias (2^s cancels in
// O/l; P <= 2^11.54 < half max). P = ex2.approx.f16x2 of packed S pairs.
// l computed by a ones-column mma on the SAME half P fragments (exact f32
// row sums, no shfl reduction needed). P never touches smem.
#define ASR 40                        // words per row
#define ATILE (64 * ASR)              // words per tile
#define ATTN_SMEM_BYTES (4 * ATILE * 4)

__global__ __launch_bounds__(256, 2) void attn_kernel() {
    extern __shared__ __align__(16) uint32_t smw[];
    uint32_t* Kw = smw;                 // [2][64][40]
    uint32_t* Vw = smw + 2 * ATILE;     // [2][64][40]

    const int tid = threadIdx.x;
    const int h = blockIdx.y;
    const int qb = (int)gridDim.x - 1 - (int)blockIdx.x;  // heavy CTAs first
    const int kvh = h >> 2;
    const int lane = tid & 31;
    const int warp = tid >> 5;
    const int gid = lane >> 2;
    const int tig = lane & 3;
    const int q0w = warp * 16;
    const int kbmax = 2 * qb + 1;

    const __half* kbase = (const __half*)g_k + (size_t)kvh * TSEQ * HDIM;
    const __half* vtbase = (const __half*)g_v + (size_t)kvh * HDIM * TSEQ;

    auto issueKV = [&](int kb) {
        const __half* kp = kbase + (size_t)kb * 64 * HDIM;
        uint32_t* Kd = Kw + (kb & 1) * ATILE;
        uint32_t* Vd = Vw + (kb & 1) * ATILE;
#pragma unroll
        for (int i = 0; i < 4; i++) {
            int slot = tid + 256 * i;           // 0..1023
            int rid = slot & 511;
            int row = rid >> 3, ch = (rid & 7) * 8;   // 8-half chunks
            if (slot < 512)
                cp16(Kd + row * ASR + (ch >> 1), kp + row * HDIM + ch);
            else
                cp16(Vd + row * ASR + (ch >> 1),
                     vtbase + (size_t)row * TSEQ + kb * 64 + ch);
        }
        asm volatile("cp.async.commit_group;");
    };

    // ---- stage Q tile (perm8 halves, verbatim), frags -> registers ----
    {
        const __half* qp = (const __half*)g_q +
                           ((size_t)h * TSEQ + (size_t)qb * 128) * HDIM;
#pragma unroll
        for (int i = 0; i < 4; i++) {
            int slot = tid + 256 * i;           // 0..1023 = 128 rows x 8 chunks
            int row = slot >> 3, ch = (slot & 7) * 8;
            *(float4*)&smw[row * ASR + (ch >> 1)] = *(const float4*)(qp + row * HDIM + ch);
        }
    }
    __syncthreads();
    uint32_t Qf[4][4];
#pragma unroll
    for (int s = 0; s < 4; s++) {
        uint2 lo = *(const uint2*)&smw[(q0w + gid) * ASR + 8 * s + 2 * tig];
        uint2 hi = *(const uint2*)&smw[(q0w + gid + 8) * ASR + 8 * s + 2 * tig];
        Qf[s][0] = lo.x; Qf[s][1] = hi.x; Qf[s][2] = lo.y; Qf[s][3] = hi.y;
    }
    __syncthreads();   // Q frags read; smem now free for K/V

    issueKV(0);

    float of[8][4];
    float lacc[4] = {0.f, 0.f, 0.f, 0.f};
#pragma unroll
    for (int ni = 0; ni < 8; ni++)
#pragma unroll
        for (int f = 0; f < 4; f++) of[ni][f] = 0.f;

    const uint32_t ones2 = 0x3C003C00u;   // half2 {1, 1}
    const int r0g = qb * 128 + q0w + gid;
    const int r1g = r0g + 8;

    for (int kb = 0; kb <= kbmax; kb++) {
        asm volatile("cp.async.wait_group 0;");
        __syncthreads();
        if (kb < kbmax) issueKV(kb + 1);

        const uint32_t* Kc = Kw + (kb & 1) * ATILE;
        const uint32_t* Vc = Vw + (kb & 1) * ATILE;
        const bool diag = (kb >= 2 * qb);

        // S chunk (8 seq cols) in log2 domain (Q pre-scaled); mask only on diag
        auto chunk = [&](int ni, float* sf) {
            sf[0] = sf[1] = sf[2] = sf[3] = 0.f;
            const uint32_t* kr = &Kc[(8 * ni + gid) * ASR + 2 * tig];
#pragma unroll
            for (int s = 0; s < 4; s++) {
                uint2 kk = *(const uint2*)&kr[8 * s];
                uint32_t b[2] = {kk.x, kk.y};
                mma_f16(sf, Qf[s], b);
            }
            if (diag) {
                int c0 = kb * 64 + 8 * ni + 2 * tig, c1 = c0 + 1;
                sf[0] = (c0 <= r0g) ? sf[0] : -INFINITY;
                sf[1] = (c1 <= r0g) ? sf[1] : -INFINITY;
                sf[2] = (c0 <= r1g) ? sf[2] : -INFINITY;
                sf[3] = (c1 <= r1g) ? sf[3] : -INFINITY;
            }
        };

#pragma unroll
        for (int j = 0; j < 4; j++) {
            float sfa[4], sfb[4];
            chunk(2 * j, sfa);
            chunk(2 * j + 1, sfb);
            // P = 2^S computed pairwise in half domain
            uint32_t a[4];
            a[0] = h2ex2(f2h2(sfa[0], sfa[1]));   // row gid,   k = 16j+2tig..+1
            a[1] = h2ex2(f2h2(sfa[2], sfa[3]));   // row gid+8
            a[2] = h2ex2(f2h2(sfb[0], sfb[1]));   // row gid,   k = 16j+8+..
            a[3] = h2ex2(f2h2(sfb[2], sfb[3]));   // row gid+8
            // l += row-sums of P (exact f32, same halves as PV)
            {
                uint32_t b[2] = {ones2, ones2};
                mma_f16(lacc, a, b);
            }
            const uint32_t* vr = &Vc[gid * ASR + 8 * j + 2 * tig];
#pragma unroll
            for (int ni = 0; ni < 8; ni++) {
                uint2 v2 = *(const uint2*)&vr[8 * ni * ASR];
                uint32_t b[2] = {v2.x, v2.y};
                mma_f16(of[ni], a, b);
            }
        }
    }

    // ---- epilogue: normalize by l (already complete per lane), store y ----
    float inv0 = 1.0f / lacc[0], inv1 = 1.0f / lacc[2];
    uint32_t* yw = (uint32_t*)g_y;
#pragma unroll
    for (int ni = 0; ni < 8; ni++) {
        int wpos = wp8(32 * h + 4 * ni + tig);
        yw[(size_t)r0g * 512 + wpos] = f2h2(of[ni][0] * inv0, of[ni][1] * inv0);
        yw[(size_t)r1g * 512 + wpos] = f2h2(of[ni][2] * inv1, of[ni][3] * inv1);
    }
}

// ---------------- launch ---------------------------------------------------
extern "C" void kernel_launch(void* const* d_in, const int* in_sizes, int n_in,
                              void* d_out, int out_size) {
    const float* x      = (const float*)d_in[0];
    const float* w_qkv  = (const float*)d_in[1];
    const float* w_proj = (const float*)d_in[2];
    const float* q_gain = (const float*)d_in[3];
    float* out = (float*)d_out;

    float *qkv_p, *y_p, *xr_p, *wq_p, *wp_p;
    cudaGetSymbolAddress((void**)&qkv_p, g_qkv);
    cudaGetSymbolAddress((void**)&y_p, g_y);
    cudaGetSymbolAddress((void**)&xr_p, g_xr);
    cudaGetSymbolAddress((void**)&wq_p, g_wq);
    cudaGetSymbolAddress((void**)&wp_p, g_wp);

    freq_kernel<<<1, 32>>>();

    round3h_kernel<<<1024, 256>>>(x, (__half*)xr_p, TSEQ * DIM / 4,
                                  w_qkv, (__half*)wq_p, QKVD * DIM / 4,
                                  w_proj, (__half*)wp_p, DIM * DIM / 4);

    cudaFuncSetAttribute(gemm_h, cudaFuncAttributeMaxDynamicSharedMemorySize,
                         GEMM_SMEM_BYTES);
    gemm_h<<<dim3(QKVD / 128, TSEQ / 128), 256, GEMM_SMEM_BYTES>>>(
        (const __half*)xr_p, (const __half*)wq_p, qkv_p, TSEQ, QKVD, DIM);

    {
        int nwarps = TSEQ * (NH + NKV);
        prep_kernel<<<nwarps / 8, 256>>>(qkv_p, q_gain);
    }
    vtrans_kernel<<<dim3(TSEQ / 32, NKV * 2), 256>>>(qkv_p);

    cudaFuncSetAttribute(attn_kernel, cudaFuncAttributeMaxDynamicSharedMemorySize,
                         ATTN_SMEM_BYTES);
    attn_kernel<<<dim3(TSEQ / 128, NH), 256, ATTN_SMEM_BYTES>>>();

    gemm_h<<<dim3(DIM / 128, TSEQ / 128), 256, GEMM_SMEM_BYTES>>>(
        (const __half*)y_p, (const __half*)wp_p, out, TSEQ, DIM, DIM);
}

// round 16
// speedup vs baseline: 1.0973x; 1.0973x over previous
#include <cuda_runtime.h>
#include <cuda_fp16.h>
#include <math.h>
#include <stdint.h>

#define TSEQ 4096
#define NH   16
#define NKV  4
#define HDIM 64
#define DIM  1024
#define QKVD 1536
#define KVOFF 1024
#define VOFF  1280

// ---------------- scratch (device globals; no cudaMalloc allowed) ----------
// float-declared, but several are used as __half (half capacity needed).
__device__ float g_qkv[TSEQ * QKVD];       // f32 (gemm1 output, prep input)
__device__ float g_q[NH * TSEQ * HDIM];    // half, d-axis word-perm8, pre-scaled by gain*cs
__device__ float g_k[NKV * TSEQ * HDIM];   // half, d-axis word-perm8
__device__ float g_v[NKV * TSEQ * HDIM];   // half, TRANSPOSED [kv][d][t], t word-perm8
__device__ float g_y[TSEQ * DIM];          // half, DIM-axis word-perm8
__device__ float g_xr[TSEQ * DIM];         // half, K-axis word-perm8
__device__ float g_wq[QKVD * DIM];         // half, K-axis word-perm8
__device__ float g_wp[DIM * DIM];          // half, K-axis word-perm8
__device__ float g_invf[32];

// ---------------- helpers ---------------------------------------------------
__device__ __forceinline__ uint32_t f2h2(float lo, float hi) {
    __half2 h = __floats2half2_rn(lo, hi);   // .x = lo half
    return *(uint32_t*)&h;
}
__device__ __forceinline__ uint32_t h2ex2(uint32_t x) {
    uint32_t r;
    asm("ex2.approx.f16x2 %0, %1;" : "=r"(r) : "r"(x));
    return r;
}
__device__ __forceinline__ void mma_f16(float c[4], const uint32_t a[4],
                                        const uint32_t b[2]) {
    asm volatile(
        "mma.sync.aligned.m16n8k16.row.col.f32.f16.f16.f32 "
        "{%0,%1,%2,%3}, {%4,%5,%6,%7}, {%8,%9}, {%0,%1,%2,%3};"
        : "+f"(c[0]), "+f"(c[1]), "+f"(c[2]), "+f"(c[3])
        : "r"(a[0]), "r"(a[1]), "r"(a[2]), "r"(a[3]), "r"(b[0]), "r"(b[1]));
}
__device__ __forceinline__ void cp16(void* smem_dst, const void* gsrc) {
    uint32_t s = (uint32_t)__cvta_generic_to_shared(smem_dst);
    asm volatile("cp.async.ca.shared.global [%0], [%1], 16;" :: "r"(s), "l"(gsrc));
}
// word-perm within each 8-word (16-half) block: word w -> 2*(w%4) + (w/4)%2
__device__ __forceinline__ int wp8(int w) {
    return (w & ~7) | ((w & 3) << 1) | ((w >> 2) & 1);
}

// ---------------- one-shot inv_freq ----------------------------------------
__global__ void freq_kernel() {
    int l = threadIdx.x;
    g_invf[l] = (float)(1.0 / pow(10000.0, (double)l * (1.0 / 32.0)));
}

// ---------------- pre-round: f32 -> f16, K-axis word-perm8 -----------------
__global__ __launch_bounds__(256) void round3h_kernel(
    const float* __restrict__ a, __half* __restrict__ da, int n1,
    const float* __restrict__ b, __half* __restrict__ db, int n2,
    const float* __restrict__ c, __half* __restrict__ dc, int n3) {
    int i = blockIdx.x * blockDim.x + threadIdx.x;
    int total = n1 + n2 + n3;
    for (; i < total; i += gridDim.x * blockDim.x) {
        const float* s;
        __half* d;
        int j = i;
        if (j < n1) { s = a; d = da; }
        else if (j < n1 + n2) { j -= n1; s = b; d = db; }
        else { j -= n1 + n2; s = c; d = dc; }
        float4 v = ((const float4*)s)[j];
        uint32_t* du = (uint32_t*)d;
        int w0 = j << 1;
        du[wp8(w0)]     = f2h2(v.x, v.y);
        du[wp8(w0 + 1)] = f2h2(v.z, v.w);
    }
}

// ---------------- fp16 GEMM: C[M,N] = A[M,K] * B[N,K]^T --------------------
// A,B half, K-axis word-perm8. 128x128 tile, 8 warps (2m x 4n), k-step 32,
// 3-stage cp.async. smem row stride 24 words (16 data + 8 pad), conflict-free.
#define GRS 24                       // words per row in smem
#define GSTG (128 * GRS)             // per-tensor per-stage words
#define GEMM_SMEM_BYTES (3 * 2 * GSTG * 4)

__global__ __launch_bounds__(256, 2) void gemm_h(const __half* __restrict__ A,
                                                 const __half* __restrict__ B,
                                                 float* __restrict__ C,
                                                 int M, int N, int K) {
    extern __shared__ __align__(16) uint32_t gsm[];
    const int tid = threadIdx.x;
    const int m0 = blockIdx.y * 128;
    const int n0 = blockIdx.x * 128;
    const int warp = tid >> 5;
    const int lane = tid & 31;
    const int gid = lane >> 2;
    const int tig = lane & 3;
    const int wm = (warp & 1) * 64;
    const int wn = (warp >> 1) * 32;

    auto issue = [&](int it) {
        int k0 = it * 32;                       // halves
        uint32_t* As = gsm + (it % 3) * 2 * GSTG;
        uint32_t* Bs = As + GSTG;
#pragma unroll
        for (int i = 0; i < 4; i++) {
            int id = tid + 256 * i;             // 0..1023
            int rid = id & 511;
            int row = rid >> 2, ch = (rid & 3) * 8;   // 8-half chunks
            const __half* src = ((id < 512)
                ? A + (size_t)(m0 + row) * K
                : B + (size_t)(n0 + row) * K) + k0 + ch;
            uint32_t* dst = ((id < 512) ? As : Bs) + row * GRS + (ch >> 1);
            cp16(dst, src);
        }
        asm volatile("cp.async.commit_group;");
    };

    float acc[4][4][4];
#pragma unroll
    for (int mi = 0; mi < 4; mi++)
#pragma unroll
        for (int ni = 0; ni < 4; ni++)
#pragma unroll
            for (int f = 0; f < 4; f++) acc[mi][ni][f] = 0.f;

    const int nIter = K / 32;
    issue(0); issue(1);

    for (int it = 0; it < nIter; it++) {
        asm volatile("cp.async.wait_group 1;");
        __syncthreads();
        if (it + 2 < nIter) issue(it + 2);
        else asm volatile("cp.async.commit_group;");

        const uint32_t* As = gsm + (it % 3) * 2 * GSTG;
        const uint32_t* Bs = As + GSTG;
#pragma unroll
        for (int s = 0; s < 2; s++) {
            uint32_t af[4][4], bf[4][2];
#pragma unroll
            for (int mi = 0; mi < 4; mi++) {
                int r = (wm + 16 * mi + gid) * GRS + 8 * s + 2 * tig;
                uint2 lo = *(const uint2*)&As[r];
                uint2 hi = *(const uint2*)&As[r + 8 * GRS];
                af[mi][0] = lo.x; af[mi][1] = hi.x;
                af[mi][2] = lo.y; af[mi][3] = hi.y;
            }
#pragma unroll
            for (int ni = 0; ni < 4; ni++) {
                uint2 b2 = *(const uint2*)&Bs[(wn + 8 * ni + gid) * GRS + 8 * s + 2 * tig];
                bf[ni][0] = b2.x; bf[ni][1] = b2.y;
            }
#pragma unroll
            for (int mi = 0; mi < 4; mi++)
#pragma unroll
                for (int ni = 0; ni < 4; ni++) mma_f16(acc[mi][ni], af[mi], bf[ni]);
        }
    }

#pragma unroll
    for (int mi = 0; mi < 4; mi++) {
        int r0 = m0 + wm + 16 * mi + gid;
#pragma unroll
        for (int ni = 0; ni < 4; ni++) {
            int c = n0 + wn + 8 * ni + 2 * tig;
            *(float2*)(C + (size_t)r0 * N + c) = make_float2(acc[mi][ni][0], acc[mi][ni][1]);
            *(float2*)(C + (size_t)(r0 + 8) * N + c) = make_float2(acc[mi][ni][2], acc[mi][ni][3]);
        }
    }
}

// ---------------- prep: RMSNorm + RoPE + gain -> half, d word-perm8 --------
// Q is additionally pre-scaled by cs = (1/8)*log2(e), so the attention S-mma
// directly produces log2-domain scores.
__global__ __launch_bounds__(256) void prep_kernel(const float* __restrict__ qkv,
                                                   const float* __restrict__ gain) {
    const int warp = blockIdx.x * 8 + (threadIdx.x >> 5);
    const int lane = threadIdx.x & 31;
    const int NQ = TSEQ * NH;
    const int NK = TSEQ * NKV;
    if (warp >= NQ + NK) return;

    const float cs = 0.18033688011112042f;
    int t, off;
    float g;
    __half* dst;
    if (warp < NQ) {
        t = warp / NH;
        int h = warp % NH;
        off = h * HDIM;
        g = gain[h] * cs;
        dst = (__half*)g_q + ((size_t)h * TSEQ + t) * HDIM;
    } else {
        int w = warp - NQ;
        t = w / NKV;
        int kv = w % NKV;
        off = KVOFF + kv * HDIM;
        g = 1.0f;
        dst = (__half*)g_k + ((size_t)kv * TSEQ + t) * HDIM;
    }
    const float* src = qkv + (size_t)t * QKVD + off;
    float x1 = src[lane], x2 = src[lane + 32];
    float ss = x1 * x1 + x2 * x2;
    ss += __shfl_xor_sync(0xffffffffu, ss, 16);
    ss += __shfl_xor_sync(0xffffffffu, ss, 8);
    ss += __shfl_xor_sync(0xffffffffu, ss, 4);
    ss += __shfl_xor_sync(0xffffffffu, ss, 2);
    ss += __shfl_xor_sync(0xffffffffu, ss, 1);
    float r = rsqrtf(ss * (1.0f / 64.0f) + 1.1920929e-07f);
    x1 *= r; x2 *= r;
    float fr = (float)t * g_invf[lane];
    float s, c;
    sincosf(fr, &s, &c);
    int e1 = lane, e2 = lane + 32;
    dst[2 * wp8(e1 >> 1) + (e1 & 1)] = __float2half_rn((x1 * c + x2 * s) * g);
    dst[2 * wp8(e2 >> 1) + (e2 & 1)] = __float2half_rn((x2 * c - x1 * s) * g);
}

// ---------------- V transpose: qkv v-slice -> half [kv][d][t], t perm8 -----
__global__ __launch_bounds__(256) void vtrans_kernel(const float* __restrict__ qkv) {
    __shared__ float ts[32][33];
    const int tx = threadIdx.x & 31;
    const int ty = threadIdx.x >> 5;
    const int t0 = blockIdx.x * 32;
    const int kv = blockIdx.y >> 1;
    const int d0 = (blockIdx.y & 1) * 32;
#pragma unroll
    for (int i = 0; i < 4; i++) {
        int row = ty + 8 * i;
        ts[row][tx] = qkv[(size_t)(t0 + row) * QKVD + VOFF + kv * HDIM + d0 + tx];
    }
    __syncthreads();
    __half* vb = (__half*)g_v + ((size_t)kv * HDIM) * TSEQ;
    int t = t0 + tx;
    int tpos = 2 * wp8(t >> 1) + (t & 1);
#pragma unroll
    for (int i = 0; i < 4; i++) {
        int d = d0 + ty + 8 * i;
        vb[(size_t)d * TSEQ + tpos] = __float2half_rn(ts[tx][ty + 8 * i]);
    }
}

// ---------------- flash attention: fp16 mma, 128-row Q tile, 4 warps -------
// Warp M-tile = 32 rows (two m16 groups) -> each K/V fragment LDS feeds TWO
// mma, halving smem crossbar traffic (was co-saturated with tensor pipe).
// Q pre-scaled by cs -> S is log2-domain; P = ex2.f16x2; l via ones-mma.
#define ASR 40                        // words per row
#define ATILE (64 * ASR)              // words per tile
#define ATTN_SMEM_BYTES (4 * ATILE * 4)

__global__ __launch_bounds__(128, 3) void attn_kernel() {
    extern __shared__ __align__(16) uint32_t smw[];
    uint32_t* Kw = smw;                 // [2][64][40]
    uint32_t* Vw = smw + 2 * ATILE;     // [2][64][40]

    const int tid = threadIdx.x;
    const int h = blockIdx.y;
    const int qb = (int)gridDim.x - 1 - (int)blockIdx.x;  // heavy CTAs first
    const int kvh = h >> 2;
    const int lane = tid & 31;
    const int warp = tid >> 5;
    const int gid = lane >> 2;
    const int tig = lane & 3;
    const int q0w = warp * 32;          // 32 rows per warp
    const int kbmax = 2 * qb + 1;

    const __half* kbase = (const __half*)g_k + (size_t)kvh * TSEQ * HDIM;
    const __half* vtbase = (const __half*)g_v + (size_t)kvh * HDIM * TSEQ;

    auto issueKV = [&](int kb) {
        const __half* kp = kbase + (size_t)kb * 64 * HDIM;
        uint32_t* Kd = Kw + (kb & 1) * ATILE;
        uint32_t* Vd = Vw + (kb & 1) * ATILE;
#pragma unroll
        for (int i = 0; i < 8; i++) {
            int slot = tid + 128 * i;           // 0..1023
            int rid = slot & 511;
            int row = rid >> 3, ch = (rid & 7) * 8;   // 8-half chunks
            if (slot < 512)
                cp16(Kd + row * ASR + (ch >> 1), kp + row * HDIM + ch);
            else
                cp16(Vd + row * ASR + (ch >> 1),
                     vtbase + (size_t)row * TSEQ + kb * 64 + ch);
        }
        asm volatile("cp.async.commit_group;");
    };

    // ---- stage Q tile (perm8 halves, verbatim), frags -> registers ----
    {
        const __half* qp = (const __half*)g_q +
                           ((size_t)h * TSEQ + (size_t)qb * 128) * HDIM;
#pragma unroll
        for (int i = 0; i < 8; i++) {
            int slot = tid + 128 * i;           // 0..1023 = 128 rows x 8 chunks
            int row = slot >> 3, ch = (slot & 7) * 8;
            *(float4*)&smw[row * ASR + (ch >> 1)] = *(const float4*)(qp + row * HDIM + ch);
        }
    }
    __syncthreads();
    uint32_t Qf[2][4][4];
#pragma unroll
    for (int m = 0; m < 2; m++)
#pragma unroll
        for (int s = 0; s < 4; s++) {
            int r = (q0w + 16 * m + gid) * ASR + 8 * s + 2 * tig;
            uint2 lo = *(const uint2*)&smw[r];
            uint2 hi = *(const uint2*)&smw[r + 8 * ASR];
            Qf[m][s][0] = lo.x; Qf[m][s][1] = hi.x;
            Qf[m][s][2] = lo.y; Qf[m][s][3] = hi.y;
        }
    __syncthreads();   // Q frags read; smem now free for K/V

    issueKV(0);

    float of[2][8][4];
    float lacc[2][4];
#pragma unroll
    for (int m = 0; m < 2; m++) {
#pragma unroll
        for (int f = 0; f < 4; f++) lacc[m][f] = 0.f;
#pragma unroll
        for (int ni = 0; ni < 8; ni++)
#pragma unroll
            for (int f = 0; f < 4; f++) of[m][ni][f] = 0.f;
    }

    const uint32_t ones2 = 0x3C003C00u;   // half2 {1, 1}
    const int rg0 = qb * 128 + q0w + gid; // m0 rows: rg0, rg0+8; m1: +16, +24

    for (int kb = 0; kb <= kbmax; kb++) {
        asm volatile("cp.async.wait_group 0;");
        __syncthreads();
        if (kb < kbmax) issueKV(kb + 1);

        const uint32_t* Kc = Kw + (kb & 1) * ATILE;
        const uint32_t* Vc = Vw + (kb & 1) * ATILE;
        const bool diag = (kb >= 2 * qb);

#pragma unroll
        for (int j = 0; j < 4; j++) {
            // ---- S chunks 2j, 2j+1 for BOTH m-tiles (K-frags shared) ----
            float sfa[2][4], sfb[2][4];
#pragma unroll
            for (int m = 0; m < 2; m++)
#pragma unroll
                for (int f = 0; f < 4; f++) { sfa[m][f] = 0.f; sfb[m][f] = 0.f; }

            const uint32_t* kra = &Kc[(16 * j + gid) * ASR + 2 * tig];
            const uint32_t* krb = kra + 8 * ASR;
#pragma unroll
            for (int s = 0; s < 4; s++) {
                uint2 ka = *(const uint2*)&kra[8 * s];
                uint2 kbv = *(const uint2*)&krb[8 * s];
                uint32_t ba[2] = {ka.x, ka.y};
                uint32_t bb[2] = {kbv.x, kbv.y};
                mma_f16(sfa[0], Qf[0][s], ba);
                mma_f16(sfa[1], Qf[1][s], ba);
                mma_f16(sfb[0], Qf[0][s], bb);
                mma_f16(sfb[1], Qf[1][s], bb);
            }

            if (diag) {
                int ca0 = kb * 64 + 16 * j + 2 * tig, ca1 = ca0 + 1;
                int cb0 = ca0 + 8, cb1 = ca1 + 8;
#pragma unroll
                for (int m = 0; m < 2; m++) {
                    int r0 = rg0 + 16 * m, r1 = r0 + 8;
                    sfa[m][0] = (ca0 <= r0) ? sfa[m][0] : -INFINITY;
                    sfa[m][1] = (ca1 <= r0) ? sfa[m][1] : -INFINITY;
                    sfa[m][2] = (ca0 <= r1) ? sfa[m][2] : -INFINITY;
                    sfa[m][3] = (ca1 <= r1) ? sfa[m][3] : -INFINITY;
                    sfb[m][0] = (cb0 <= r0) ? sfb[m][0] : -INFINITY;
                    sfb[m][1] = (cb1 <= r0) ? sfb[m][1] : -INFINITY;
                    sfb[m][2] = (cb0 <= r1) ? sfb[m][2] : -INFINITY;
                    sfb[m][3] = (cb1 <= r1) ? sfb[m][3] : -INFINITY;
                }
            }

            // ---- P = 2^S (f16x2), l += row-sums, O += P V ----
            uint32_t a[2][4];
#pragma unroll
            for (int m = 0; m < 2; m++) {
                a[m][0] = h2ex2(f2h2(sfa[m][0], sfa[m][1]));
                a[m][1] = h2ex2(f2h2(sfa[m][2], sfa[m][3]));
                a[m][2] = h2ex2(f2h2(sfb[m][0], sfb[m][1]));
                a[m][3] = h2ex2(f2h2(sfb[m][2], sfb[m][3]));
                uint32_t bo[2] = {ones2, ones2};
                mma_f16(lacc[m], a[m], bo);
            }
            const uint32_t* vr = &Vc[gid * ASR + 8 * j + 2 * tig];
#pragma unroll
            for (int ni = 0; ni < 8; ni++) {
                uint2 v2 = *(const uint2*)&vr[8 * ni * ASR];
                uint32_t b[2] = {v2.x, v2.y};
                mma_f16(of[0][ni], a[0], b);
                mma_f16(of[1][ni], a[1], b);
            }
        }
    }

    // ---- epilogue: normalize by l, store y half (DIM word-perm8) ----
    uint32_t* yw = (uint32_t*)g_y;
#pragma unroll
    for (int m = 0; m < 2; m++) {
        float inv0 = 1.0f / lacc[m][0], inv1 = 1.0f / lacc[m][2];
        size_t r0 = (size_t)(rg0 + 16 * m) * 512;
        size_t r1 = (size_t)(rg0 + 16 * m + 8) * 512;
#pragma unroll
        for (int ni = 0; ni < 8; ni++) {
            int wpos = wp8(32 * h + 4 * ni + tig);
            yw[r0 + wpos] = f2h2(of[m][ni][0] * inv0, of[m][ni][1] * inv0);
            yw[r1 + wpos] = f2h2(of[m][ni][2] * inv1, of[m][ni][3] * inv1);
        }
    }
}

// ---------------- launch ---------------------------------------------------
extern "C" void kernel_launch(void* const* d_in, const int* in_sizes, int n_in,
                              void* d_out, int out_size) {
    const float* x      = (const float*)d_in[0];
    const float* w_qkv  = (const float*)d_in[1];
    const float* w_proj = (const float*)d_in[2];
    const float* q_gain = (const float*)d_in[3];
    float* out = (float*)d_out;

    float *qkv_p, *y_p, *xr_p, *wq_p, *wp_p;
    cudaGetSymbolAddress((void**)&qkv_p, g_qkv);
    cudaGetSymbolAddress((void**)&y_p, g_y);
    cudaGetSymbolAddress((void**)&xr_p, g_xr);
    cudaGetSymbolAddress((void**)&wq_p, g_wq);
    cudaGetSymbolAddress((void**)&wp_p, g_wp);

    freq_kernel<<<1, 32>>>();

    round3h_kernel<<<1024, 256>>>(x, (__half*)xr_p, TSEQ * DIM / 4,
                                  w_qkv, (__half*)wq_p, QKVD * DIM / 4,
                                  w_proj, (__half*)wp_p, DIM * DIM / 4);

    cudaFuncSetAttribute(gemm_h, cudaFuncAttributeMaxDynamicSharedMemorySize,
                         GEMM_SMEM_BYTES);
    gemm_h<<<dim3(QKVD / 128, TSEQ / 128), 256, GEMM_SMEM_BYTES>>>(
        (const __half*)xr_p, (const __half*)wq_p, qkv_p, TSEQ, QKVD, DIM);

    {
        int nwarps = TSEQ * (NH + NKV);
        prep_kernel<<<nwarps / 8, 256>>>(qkv_p, q_gain);
    }
    vtrans_kernel<<<dim3(TSEQ / 32, NKV * 2), 256>>>(qkv_p);

    cudaFuncSetAttribute(attn_kernel, cudaFuncAttributeMaxDynamicSharedMemorySize,
                         ATTN_SMEM_BYTES);
    attn_kernel<<<dim3(TSEQ / 128, NH), 128, ATTN_SMEM_BYTES>>>();

    gemm_h<<<dim3(DIM / 128, TSEQ / 128), 256, GEMM_SMEM_BYTES>>>(
        (const __half*)y_p, (const __half*)wp_p, out, TSEQ, DIM, DIM);
}

// round 17
// speedup vs baseline: 1.1007x; 1.0031x over previous
#include <cuda_runtime.h>
#include <cuda_fp16.h>
#include <math.h>
#include <stdint.h>

#define TSEQ 4096
#define NH   16
#define NKV  4
#define HDIM 64
#define DIM  1024
#define QKVD 1536
#define KVOFF 1024
#define VOFF  1280

// ---------------- scratch (device globals; no cudaMalloc allowed) ----------
__device__ float g_qkv[TSEQ * QKVD];       // f32 (gemm1 output, prep input)
__device__ float g_q[NH * TSEQ * HDIM];    // half, d-axis word-perm8, pre-scaled by gain*cs
__device__ float g_k[NKV * TSEQ * HDIM];   // half, d-axis word-perm8
__device__ float g_v[NKV * TSEQ * HDIM];   // half, TRANSPOSED [kv][d][t], t word-perm8
__device__ float g_y[TSEQ * DIM];          // half, DIM-axis word-perm8
__device__ float g_xr[TSEQ * DIM];         // half, K-axis word-perm8
__device__ float g_wq[QKVD * DIM];         // half, K-axis word-perm8
__device__ float g_wp[DIM * DIM];          // half, K-axis word-perm8
__device__ float g_invf[32];

// ---------------- helpers ---------------------------------------------------
__device__ __forceinline__ uint32_t f2h2(float lo, float hi) {
    __half2 h = __floats2half2_rn(lo, hi);   // .x = lo half
    return *(uint32_t*)&h;
}
__device__ __forceinline__ uint32_t h2ex2(uint32_t x) {
    uint32_t r;
    asm("ex2.approx.f16x2 %0, %1;" : "=r"(r) : "r"(x));
    return r;
}
__device__ __forceinline__ void mma_f16(float c[4], const uint32_t a[4],
                                        const uint32_t b[2]) {
    asm volatile(
        "mma.sync.aligned.m16n8k16.row.col.f32.f16.f16.f32 "
        "{%0,%1,%2,%3}, {%4,%5,%6,%7}, {%8,%9}, {%0,%1,%2,%3};"
        : "+f"(c[0]), "+f"(c[1]), "+f"(c[2]), "+f"(c[3])
        : "r"(a[0]), "r"(a[1]), "r"(a[2]), "r"(a[3]), "r"(b[0]), "r"(b[1]));
}
__device__ __forceinline__ void cp16(void* smem_dst, const void* gsrc) {
    uint32_t s = (uint32_t)__cvta_generic_to_shared(smem_dst);
    asm volatile("cp.async.ca.shared.global [%0], [%1], 16;" :: "r"(s), "l"(gsrc));
}
// word-perm within each 8-word (16-half) block: word w -> 2*(w%4) + (w/4)%2
__device__ __forceinline__ int wp8(int w) {
    return (w & ~7) | ((w & 3) << 1) | ((w >> 2) & 1);
}

// ---------------- pre-round: f32 -> f16, K-axis word-perm8 (+inv_freq) -----
__global__ __launch_bounds__(256) void round3h_kernel(
    const float* __restrict__ a, __half* __restrict__ da, int n1,
    const float* __restrict__ b, __half* __restrict__ db, int n2,
    const float* __restrict__ c, __half* __restrict__ dc, int n3) {
    if (blockIdx.x == 0 && threadIdx.x < 32)
        g_invf[threadIdx.x] =
            (float)(1.0 / pow(10000.0, (double)threadIdx.x * (1.0 / 32.0)));
    int i = blockIdx.x * blockDim.x + threadIdx.x;
    int total = n1 + n2 + n3;
    for (; i < total; i += gridDim.x * blockDim.x) {
        const float* s;
        __half* d;
        int j = i;
        if (j < n1) { s = a; d = da; }
        else if (j < n1 + n2) { j -= n1; s = b; d = db; }
        else { j -= n1 + n2; s = c; d = dc; }
        float4 v = ((const float4*)s)[j];
        uint32_t* du = (uint32_t*)d;
        int w0 = j << 1;
        du[wp8(w0)]     = f2h2(v.x, v.y);
        du[wp8(w0 + 1)] = f2h2(v.z, v.w);
    }
}

// ---------------- fp16 GEMM: C[M,N] = A[M,K] * B[N,K]^T --------------------
// A,B half, K-axis word-perm8. 128x128 tile, 8 warps (2m x 4n), k-step 32,
// 3-stage cp.async. smem row stride 24 words (16 data + 8 pad), conflict-free.
#define GRS 24                       // words per row in smem
#define GSTG (128 * GRS)             // per-tensor per-stage words
#define GEMM_SMEM_BYTES (3 * 2 * GSTG * 4)

__global__ __launch_bounds__(256, 2) void gemm_h(const __half* __restrict__ A,
                                                 const __half* __restrict__ B,
                                                 float* __restrict__ C,
                                                 int M, int N, int K) {
    extern __shared__ __align__(16) uint32_t gsm[];
    const int tid = threadIdx.x;
    const int m0 = blockIdx.y * 128;
    const int n0 = blockIdx.x * 128;
    const int warp = tid >> 5;
    const int lane = tid & 31;
    const int gid = lane >> 2;
    const int tig = lane & 3;
    const int wm = (warp & 1) * 64;
    const int wn = (warp >> 1) * 32;

    auto issue = [&](int it) {
        int k0 = it * 32;                       // halves
        uint32_t* As = gsm + (it % 3) * 2 * GSTG;
        uint32_t* Bs = As + GSTG;
#pragma unroll
        for (int i = 0; i < 4; i++) {
            int id = tid + 256 * i;             // 0..1023
            int rid = id & 511;
            int row = rid >> 2, ch = (rid & 3) * 8;   // 8-half chunks
            const __half* src = ((id < 512)
                ? A + (size_t)(m0 + row) * K
                : B + (size_t)(n0 + row) * K) + k0 + ch;
            uint32_t* dst = ((id < 512) ? As : Bs) + row * GRS + (ch >> 1);
            cp16(dst, src);
        }
        asm volatile("cp.async.commit_group;");
    };

    float acc[4][4][4];
#pragma unroll
    for (int mi = 0; mi < 4; mi++)
#pragma unroll
        for (int ni = 0; ni < 4; ni++)
#pragma unroll
            for (int f = 0; f < 4; f++) acc[mi][ni][f] = 0.f;

    const int nIter = K / 32;
    issue(0); issue(1);

    for (int it = 0; it < nIter; it++) {
        asm volatile("cp.async.wait_group 1;");
        __syncthreads();
        if (it + 2 < nIter) issue(it + 2);
        else asm volatile("cp.async.commit_group;");

        const uint32_t* As = gsm + (it % 3) * 2 * GSTG;
        const uint32_t* Bs = As + GSTG;
#pragma unroll
        for (int s = 0; s < 2; s++) {
            uint32_t af[4][4], bf[4][2];
#pragma unroll
            for (int mi = 0; mi < 4; mi++) {
                int r = (wm + 16 * mi + gid) * GRS + 8 * s + 2 * tig;
                uint2 lo = *(const uint2*)&As[r];
                uint2 hi = *(const uint2*)&As[r + 8 * GRS];
                af[mi][0] = lo.x; af[mi][1] = hi.x;
                af[mi][2] = lo.y; af[mi][3] = hi.y;
            }
#pragma unroll
            for (int ni = 0; ni < 4; ni++) {
                uint2 b2 = *(const uint2*)&Bs[(wn + 8 * ni + gid) * GRS + 8 * s + 2 * tig];
                bf[ni][0] = b2.x; bf[ni][1] = b2.y;
            }
#pragma unroll
            for (int mi = 0; mi < 4; mi++)
#pragma unroll
                for (int ni = 0; ni < 4; ni++) mma_f16(acc[mi][ni], af[mi], bf[ni]);
        }
    }

#pragma unroll
    for (int mi = 0; mi < 4; mi++) {
        int r0 = m0 + wm + 16 * mi + gid;
#pragma unroll
        for (int ni = 0; ni < 4; ni++) {
            int c = n0 + wn + 8 * ni + 2 * tig;
            *(float2*)(C + (size_t)r0 * N + c) = make_float2(acc[mi][ni][0], acc[mi][ni][1]);
            *(float2*)(C + (size_t)(r0 + 8) * N + c) = make_float2(acc[mi][ni][2], acc[mi][ni][3]);
        }
    }
}

// ---------------- fused prep (RMSNorm+RoPE+gain) + V transpose -------------
// blocks [0, NPREP): q/k rows -> half, d word-perm8 (Q pre-scaled by cs).
// blocks [NPREP, NPREP+NVT): V transpose -> half [kv][d][t], t word-perm8.
#define NPREP (TSEQ * (NH + NKV) / 8)       // 10240
#define NVT   (TSEQ / 32 * NKV * 2)         // 1024

__global__ __launch_bounds__(256) void prepv_kernel(const float* __restrict__ qkv,
                                                    const float* __restrict__ gain) {
    __shared__ float ts[32][33];
    if (blockIdx.x < NPREP) {
        const int warp = blockIdx.x * 8 + (threadIdx.x >> 5);
        const int lane = threadIdx.x & 31;
        const int NQ = TSEQ * NH;

        const float cs = 0.18033688011112042f;
        int t, off;
        float g;
        __half* dst;
        if (warp < NQ) {
            t = warp / NH;
            int h = warp % NH;
            off = h * HDIM;
            g = gain[h] * cs;
            dst = (__half*)g_q + ((size_t)h * TSEQ + t) * HDIM;
        } else {
            int w = warp - NQ;
            t = w / NKV;
            int kv = w % NKV;
            off = KVOFF + kv * HDIM;
            g = 1.0f;
            dst = (__half*)g_k + ((size_t)kv * TSEQ + t) * HDIM;
        }
        const float* src = qkv + (size_t)t * QKVD + off;
        float x1 = src[lane], x2 = src[lane + 32];
        float ss = x1 * x1 + x2 * x2;
        ss += __shfl_xor_sync(0xffffffffu, ss, 16);
        ss += __shfl_xor_sync(0xffffffffu, ss, 8);
        ss += __shfl_xor_sync(0xffffffffu, ss, 4);
        ss += __shfl_xor_sync(0xffffffffu, ss, 2);
        ss += __shfl_xor_sync(0xffffffffu, ss, 1);
        float r = rsqrtf(ss * (1.0f / 64.0f) + 1.1920929e-07f);
        x1 *= r; x2 *= r;
        float fr = (float)t * g_invf[lane];
        float s, c;
        sincosf(fr, &s, &c);
        float o1 = (x1 * c + x2 * s) * g;
        float o2 = (x2 * c - x1 * s) * g;
        // pair 2B halves into 4B word stores (even lanes write)
        uint32_t w1 = f2h2(o1, __shfl_down_sync(0xffffffffu, o1, 1));
        uint32_t w2 = f2h2(o2, __shfl_down_sync(0xffffffffu, o2, 1));
        if (!(lane & 1)) {
            uint32_t* dw = (uint32_t*)dst;
            int i = lane >> 1;
            dw[wp8(i)] = w1;
            dw[wp8(16 + i)] = w2;
        }
    } else {
        const int vb = blockIdx.x - NPREP;
        const int tx = threadIdx.x & 31;
        const int ty = threadIdx.x >> 5;
        const int t0 = (vb & 127) * 32;
        const int g2 = vb >> 7;             // 0..7
        const int kv = g2 >> 1;
        const int d0 = (g2 & 1) * 32;
#pragma unroll
        for (int i = 0; i < 4; i++) {
            int row = ty + 8 * i;
            ts[row][tx] = qkv[(size_t)(t0 + row) * QKVD + VOFF + kv * HDIM + d0 + tx];
        }
        __syncthreads();
        __half* vbp = (__half*)g_v + ((size_t)kv * HDIM) * TSEQ;
        int t = t0 + tx;
        int tpos = 2 * wp8(t >> 1) + (t & 1);
#pragma unroll
        for (int i = 0; i < 4; i++) {
            int d = d0 + ty + 8 * i;
            vbp[(size_t)d * TSEQ + tpos] = __float2half_rn(ts[tx][ty + 8 * i]);
        }
    }
}

// ---------------- flash attention: fp16 mma, 128-row Q tile, 4 warps -------
// Warp M-tile = 32 rows; K/V frags shared across both m16 groups.
// Triple-buffered K/V (2-deep cp.async prefetch, wait_group 1).
// Q pre-scaled by cs -> S is log2-domain; P = ex2.f16x2; l via ones-mma.
#define ASR 40                        // words per row
#define ATILE (64 * ASR)              // words per tile
#define ATTN_SMEM_BYTES (6 * ATILE * 4)

__global__ __launch_bounds__(128, 3) void attn_kernel() {
    extern __shared__ __align__(16) uint32_t smw[];
    uint32_t* Kw = smw;                 // [3][64][40]
    uint32_t* Vw = smw + 3 * ATILE;     // [3][64][40]

    const int tid = threadIdx.x;
    const int h = blockIdx.y;
    const int qb = (int)gridDim.x - 1 - (int)blockIdx.x;  // heavy CTAs first
    const int kvh = h >> 2;
    const int lane = tid & 31;
    const int warp = tid >> 5;
    const int gid = lane >> 2;
    const int tig = lane & 3;
    const int q0w = warp * 32;          // 32 rows per warp
    const int kbmax = 2 * qb + 1;

    const __half* kbase = (const __half*)g_k + (size_t)kvh * TSEQ * HDIM;
    const __half* vtbase = (const __half*)g_v + (size_t)kvh * HDIM * TSEQ;

    auto issueKV = [&](int kb) {
        const __half* kp = kbase + (size_t)kb * 64 * HDIM;
        int buf = kb % 3;
        uint32_t* Kd = Kw + buf * ATILE;
        uint32_t* Vd = Vw + buf * ATILE;
#pragma unroll
        for (int i = 0; i < 8; i++) {
            int slot = tid + 128 * i;           // 0..1023
            int rid = slot & 511;
            int row = rid >> 3, ch = (rid & 7) * 8;   // 8-half chunks
            if (slot < 512)
                cp16(Kd + row * ASR + (ch >> 1), kp + row * HDIM + ch);
            else
                cp16(Vd + row * ASR + (ch >> 1),
                     vtbase + (size_t)row * TSEQ + kb * 64 + ch);
        }
        asm volatile("cp.async.commit_group;");
    };

    // ---- stage Q tile (perm8 halves, verbatim), frags -> registers ----
    {
        const __half* qp = (const __half*)g_q +
                           ((size_t)h * TSEQ + (size_t)qb * 128) * HDIM;
#pragma unroll
        for (int i = 0; i < 8; i++) {
            int slot = tid + 128 * i;           // 0..1023 = 128 rows x 8 chunks
            int row = slot >> 3, ch = (slot & 7) * 8;
            *(float4*)&smw[row * ASR + (ch >> 1)] = *(const float4*)(qp + row * HDIM + ch);
        }
    }
    __syncthreads();
    uint32_t Qf[2][4][4];
#pragma unroll
    for (int m = 0; m < 2; m++)
#pragma unroll
        for (int s = 0; s < 4; s++) {
            int r = (q0w + 16 * m + gid) * ASR + 8 * s + 2 * tig;
            uint2 lo = *(const uint2*)&smw[r];
            uint2 hi = *(const uint2*)&smw[r + 8 * ASR];
            Qf[m][s][0] = lo.x; Qf[m][s][1] = hi.x;
            Qf[m][s][2] = lo.y; Qf[m][s][3] = hi.y;
        }
    __syncthreads();   // Q frags read; smem now free for K/V

    issueKV(0);
    if (kbmax >= 1) issueKV(1);
    else asm volatile("cp.async.commit_group;");

    float of[2][8][4];
    float lacc[2][4];
#pragma unroll
    for (int m = 0; m < 2; m++) {
#pragma unroll
        for (int f = 0; f < 4; f++) lacc[m][f] = 0.f;
#pragma unroll
        for (int ni = 0; ni < 8; ni++)
#pragma unroll
            for (int f = 0; f < 4; f++) of[m][ni][f] = 0.f;
    }

    const uint32_t ones2 = 0x3C003C00u;   // half2 {1, 1}
    const int rg0 = qb * 128 + q0w + gid; // m0 rows: rg0, rg0+8; m1: +16, +24

    for (int kb = 0; kb <= kbmax; kb++) {
        asm volatile("cp.async.wait_group 1;");
        __syncthreads();
        if (kb + 2 <= kbmax) issueKV(kb + 2);
        else asm volatile("cp.async.commit_group;");

        int buf = kb % 3;
        const uint32_t* Kc = Kw + buf * ATILE;
        const uint32_t* Vc = Vw + buf * ATILE;
        const bool diag = (kb >= 2 * qb);

#pragma unroll
        for (int j = 0; j < 4; j++) {
            // ---- S chunks 2j, 2j+1 for BOTH m-tiles (K-frags shared) ----
            float sfa[2][4], sfb[2][4];
#pragma unroll
            for (int m = 0; m < 2; m++)
#pragma unroll
                for (int f = 0; f < 4; f++) { sfa[m][f] = 0.f; sfb[m][f] = 0.f; }

            const uint32_t* kra = &Kc[(16 * j + gid) * ASR + 2 * tig];
            const uint32_t* krb = kra + 8 * ASR;
#pragma unroll
            for (int s = 0; s < 4; s++) {
                uint2 ka = *(const uint2*)&kra[8 * s];
                uint2 kbv = *(const uint2*)&krb[8 * s];
                uint32_t ba[2] = {ka.x, ka.y};
                uint32_t bb[2] = {kbv.x, kbv.y};
                mma_f16(sfa[0], Qf[0][s], ba);
                mma_f16(sfa[1], Qf[1][s], ba);
                mma_f16(sfb[0], Qf[0][s], bb);
                mma_f16(sfb[1], Qf[1][s], bb);
            }

            if (diag) {
                int ca0 = kb * 64 + 16 * j + 2 * tig, ca1 = ca0 + 1;
                int cb0 = ca0 + 8, cb1 = ca1 + 8;
#pragma unroll
                for (int m = 0; m < 2; m++) {
                    int r0 = rg0 + 16 * m, r1 = r0 + 8;
                    sfa[m][0] = (ca0 <= r0) ? sfa[m][0] : -INFINITY;
                    sfa[m][1] = (ca1 <= r0) ? sfa[m][1] : -INFINITY;
                    sfa[m][2] = (ca0 <= r1) ? sfa[m][2] : -INFINITY;
                    sfa[m][3] = (ca1 <= r1) ? sfa[m][3] : -INFINITY;
                    sfb[m][0] = (cb0 <= r0) ? sfb[m][0] : -INFINITY;
                    sfb[m][1] = (cb1 <= r0) ? sfb[m][1] : -INFINITY;
                    sfb[m][2] = (cb0 <= r1) ? sfb[m][2] : -INFINITY;
                    sfb[m][3] = (cb1 <= r1) ? sfb[m][3] : -INFINITY;
                }
            }

            // ---- P = 2^S (f16x2), l += row-sums, O += P V ----
            uint32_t a[2][4];
#pragma unroll
            for (int m = 0; m < 2; m++) {
                a[m][0] = h2ex2(f2h2(sfa[m][0], sfa[m][1]));
                a[m][1] = h2ex2(f2h2(sfa[m][2], sfa[m][3]));
                a[m][2] = h2ex2(f2h2(sfb[m][0], sfb[m][1]));
                a[m][3] = h2ex2(f2h2(sfb[m][2], sfb[m][3]));
                uint32_t bo[2] = {ones2, ones2};
                mma_f16(lacc[m], a[m], bo);
            }
            const uint32_t* vr = &Vc[gid * ASR + 8 * j + 2 * tig];
#pragma unroll
            for (int ni = 0; ni < 8; ni++) {
                uint2 v2 = *(const uint2*)&vr[8 * ni * ASR];
                uint32_t b[2] = {v2.x, v2.y};
                mma_f16(of[0][ni], a[0], b);
                mma_f16(of[1][ni], a[1], b);
            }
        }
    }

    // ---- epilogue: normalize by l, store y half (DIM word-perm8) ----
    uint32_t* yw = (uint32_t*)g_y;
#pragma unroll
    for (int m = 0; m < 2; m++) {
        float inv0 = 1.0f / lacc[m][0], inv1 = 1.0f / lacc[m][2];
        size_t r0 = (size_t)(rg0 + 16 * m) * 512;
        size_t r1 = (size_t)(rg0 + 16 * m + 8) * 512;
#pragma unroll
        for (int ni = 0; ni < 8; ni++) {
            int wpos = wp8(32 * h + 4 * ni + tig);
            yw[r0 + wpos] = f2h2(of[m][ni][0] * inv0, of[m][ni][1] * inv0);
            yw[r1 + wpos] = f2h2(of[m][ni][2] * inv1, of[m][ni][3] * inv1);
        }
    }
}

// ---------------- launch ---------------------------------------------------
extern "C" void kernel_launch(void* const* d_in, const int* in_sizes, int n_in,
                              void* d_out, int out_size) {
    const float* x      = (const float*)d_in[0];
    const float* w_qkv  = (const float*)d_in[1];
    const float* w_proj = (const float*)d_in[2];
    const float* q_gain = (const float*)d_in[3];
    float* out = (float*)d_out;

    float *qkv_p, *y_p, *xr_p, *wq_p, *wp_p;
    cudaGetSymbolAddress((void**)&qkv_p, g_qkv);
    cudaGetSymbolAddress((void**)&y_p, g_y);
    cudaGetSymbolAddress((void**)&xr_p, g_xr);
    cudaGetSymbolAddress((void**)&wq_p, g_wq);
    cudaGetSymbolAddress((void**)&wp_p, g_wp);

    round3h_kernel<<<1024, 256>>>(x, (__half*)xr_p, TSEQ * DIM / 4,
                                  w_qkv, (__half*)wq_p, QKVD * DIM / 4,
                                  w_proj, (__half*)wp_p, DIM * DIM / 4);

    cudaFuncSetAttribute(gemm_h, cudaFuncAttributeMaxDynamicSharedMemorySize,
                         GEMM_SMEM_BYTES);
    gemm_h<<<dim3(QKVD / 128, TSEQ / 128), 256, GEMM_SMEM_BYTES>>>(
        (const __half*)xr_p, (const __half*)wq_p, qkv_p, TSEQ, QKVD, DIM);

    prepv_kernel<<<NPREP + NVT, 256>>>(qkv_p, q_gain);

    cudaFuncSetAttribute(attn_kernel, cudaFuncAttributeMaxDynamicSharedMemorySize,
                         ATTN_SMEM_BYTES);
    attn_kernel<<<dim3(TSEQ / 128, NH), 128, ATTN_SMEM_BYTES>>>();

    gemm_h<<<dim3(DIM / 128, TSEQ / 128), 256, GEMM_SMEM_BYTES>>>(
        (const __half*)y_p, (const __half*)wp_p, out, TSEQ, DIM, DIM);
}